// round 2
// baseline (speedup 1.0000x reference)
#include <cuda_runtime.h>
#include <cstdint>

// ---------------------------------------------------------------------------
// HiPPO-LegT scan:  c_t = A c_{t-1} + f_t * B,  per (b,d) sequence.
// inputs: (16,128,512) f32; A: (64,64) f32; B: (64,) f32
// out:    (512, 16, 128, 64) f32  -> out[((t*2048)+bd)*64 + n]
//
// One 64-thread block per sequence; thread n owns state row n.
// A row n held in registers as 32 packed f32x2 (over m).  State c in shared,
// double buffered, read back as broadcast 16B vector loads (pre-packed f32
// pairs).  Math via Blackwell packed fma.rn.f32x2 (double-rate vs FFMA).
// 4 independent accumulator chains of depth 8 -> short critical path; ~90
// regs/thread -> ~20+ warps/SM for latency hiding.
// ---------------------------------------------------------------------------

__device__ __forceinline__ double fma2(double a, double b, double c) {
    double d;
    asm("fma.rn.f32x2 %0, %1, %2, %3;" : "=d"(d) : "d"(a), "d"(b), "d"(c));
    return d;
}
__device__ __forceinline__ double add2(double a, double b) {
    double d;
    asm("add.rn.f32x2 %0, %1, %2;" : "=d"(d) : "d"(a), "d"(b));
    return d;
}
__device__ __forceinline__ void unpack2(double d, float& lo, float& hi) {
    asm("mov.b64 {%0, %1}, %2;" : "=f"(lo), "=f"(hi) : "d"(d));
}

static constexpr int SEQ_LEN  = 512;
static constexpr int NSTATE   = 64;
static constexpr int BD_TOTAL = 2048;   // 16 * 128

__global__ __launch_bounds__(NSTATE)
void hippo_scan_kernel(const float* __restrict__ xin,
                       const float* __restrict__ Amat,
                       const float* __restrict__ Bvec,
                       float* __restrict__ out)
{
    const int bd = blockIdx.x;
    const int n  = threadIdx.x;          // state row owned by this thread

    __shared__ __align__(16) float c_sm[2][NSTATE];
    __shared__ float f_sm[SEQ_LEN];

    // Preload this sequence's 512 f values.
    {
        const float4* src = reinterpret_cast<const float4*>(xin + (size_t)bd * SEQ_LEN);
        float4* dst = reinterpret_cast<float4*>(f_sm);
        #pragma unroll
        for (int i = 0; i < SEQ_LEN / 4 / NSTATE; i++)
            dst[n + NSTATE * i] = src[n + NSTATE * i];
    }

    // Preload A row n as 32 packed f32 pairs (over m): 64 registers.
    double a[NSTATE / 2];
    {
        const double* r = reinterpret_cast<const double*>(Amat + (size_t)n * NSTATE);
        #pragma unroll
        for (int i = 0; i < NSTATE / 2; i++) a[i] = r[i];
    }
    const float b = Bvec[n];

    c_sm[0][n] = 0.0f;
    __syncthreads();

    float* op = out + (size_t)bd * NSTATE + n;

    #pragma unroll 2
    for (int t = 0; t < SEQ_LEN; t++) {
        const int cur = t & 1;
        const float f = f_sm[t];
        const double2* cs = reinterpret_cast<const double2*>(c_sm[cur]);

        // 4 independent chains of depth 8 over the 32 packed pairs.
        double acc0 = 0.0, acc1 = 0.0, acc2 = 0.0, acc3 = 0.0;
        #pragma unroll
        for (int i = 0; i < 8; i++) {
            const double2 cva = cs[2 * i];          // pairs (4i..4i+3)
            const double2 cvb = cs[2 * i + 1];      // pairs (4i+4..4i+7)
            acc0 = fma2(a[4 * i],     cva.x, acc0);
            acc1 = fma2(a[4 * i + 1], cva.y, acc1);
            acc2 = fma2(a[4 * i + 2], cvb.x, acc2);
            acc3 = fma2(a[4 * i + 3], cvb.y, acc3);
        }
        const double s = add2(add2(acc0, acc1), add2(acc2, acc3));
        float x, y;
        unpack2(s, x, y);
        const float cn = fmaf(f, b, x + y);

        c_sm[cur ^ 1][n] = cn;                      // publish new state
        __syncthreads();

        *op = cn;                                   // coalesced 256B/block store
        op += (size_t)BD_TOTAL * NSTATE;
    }
}

extern "C" void kernel_launch(void* const* d_in, const int* in_sizes, int n_in,
                              void* d_out, int out_size)
{
    const float* xin  = (const float*)d_in[0];  // (16,128,512)
    const float* Amat = (const float*)d_in[1];  // (64,64)
    const float* Bvec = (const float*)d_in[2];  // (64,)
    float* out = (float*)d_out;                 // (512,16,128,64)

    hippo_scan_kernel<<<BD_TOTAL, NSTATE>>>(xin, Amat, Bvec, out);
}